// round 1
// baseline (speedup 1.0000x reference)
#include <cuda_runtime.h>
#include <stdint.h>

#define WIN 32
#define NPX 1024
#define NH 992
#define NEDGE 1984
#define SORTN 2048
#define NTHREADS 256

struct Smem {
    float pred[NPX];
    float tv[NPX];
    unsigned long long sortbuf[SORTN];
    float w0[NEDGE];
    float w1[NEDGE];
    unsigned short order0[NEDGE];
    unsigned short order1[NEDGE];
    unsigned short lab[NPX];
    unsigned char eflags[NEDGE];
    unsigned char mA[NPX];
    unsigned char mB[NPX];
    // union-find + label-count pools, one set per run (0 = neg, 1 = pos)
    unsigned short parent[2][NPX];
    unsigned short tot[2][NPX];
    unsigned short nent[2][NPX];
    short head[2][NPX];
    unsigned short elab[2][NPX];
    unsigned short ecnt[2][NPX];
    short enext[2][NPX];
    int changed;
    float red[NTHREADS];
};

__device__ __forceinline__ void edge_nodes(int e, int& n1, int& n2) {
    if (e < NH) {
        int r = e / 31;
        int c = e - r * 31;
        n1 = (r << 5) + c;
        n2 = n1 + 1;
    } else {
        n1 = e - NH;
        n2 = n1 + 32;
    }
}

__device__ __forceinline__ int uf_find(unsigned short* par, int x) {
    while (par[x] != x) {
        par[x] = par[par[x]];   // path halving
        x = par[x];
    }
    return x;
}

__device__ void bitonic_sort(Smem* s) {
    int tid = threadIdx.x;
    for (int k = 2; k <= SORTN; k <<= 1) {
        for (int jj = k >> 1; jj > 0; jj >>= 1) {
            for (int i = tid; i < SORTN; i += NTHREADS) {
                int p = i ^ jj;
                if (p > i) {
                    unsigned long long a = s->sortbuf[i];
                    unsigned long long b = s->sortbuf[p];
                    bool up = ((i & k) == 0);
                    if ((a > b) == up) {
                        s->sortbuf[i] = b;
                        s->sortbuf[p] = a;
                    }
                }
            }
            __syncthreads();
        }
    }
}

// Serial Kruskal with per-component label-count linked lists.
// Weights depend only on the partition sequence (which is fixed by the sorted
// edge order), so union direction / iteration side do not change the result.
__device__ void kruskal(Smem* s, int run, const unsigned short* order, bool pos) {
    unsigned short* par  = s->parent[run];
    unsigned short* tot  = s->tot[run];
    unsigned short* nent = s->nent[run];
    short* head          = s->head[run];
    unsigned short* elab = s->elab[run];
    unsigned short* ecnt = s->ecnt[run];
    short* enext         = s->enext[run];
    float* w = run ? s->w1 : s->w0;

    for (int oi = 0; oi < NEDGE; oi++) {
        int e = order[oi];
        int n1, n2;
        edge_nodes(e, n1, n2);
        int ra = uf_find(par, n1);
        int rb = uf_find(par, n2);
        if (ra == rb) continue;

        // small-to-large by number of distinct labels (perf only)
        int rs, rl;
        if (nent[ra] <= nent[rb]) { rs = ra; rl = rb; }
        else                      { rs = rb; rl = ra; }

        unsigned sa = tot[ra];
        unsigned sb = tot[rb];
        unsigned same = 0;

        int pe = head[rs];
        while (pe >= 0) {
            int nx = enext[pe];
            unsigned short L = elab[pe];
            int q = head[rl];
            int found = 0;
            while (q >= 0) {
                if (elab[q] == L) {
                    same += (unsigned)ecnt[pe] * (unsigned)ecnt[q];
                    ecnt[q] = (unsigned short)(ecnt[q] + ecnt[pe]);
                    found = 1;
                    break;
                }
                q = enext[q];
            }
            if (!found) {
                enext[pe] = head[rl];
                head[rl] = (short)pe;
                nent[rl]++;
            }
            pe = nx;
        }

        w[e] = pos ? (float)same : (float)(sa * sb - same);
        par[rs] = (unsigned short)rl;
        tot[rl] = (unsigned short)(sa + sb);
    }
}

__device__ float block_reduce(Smem* s, float v) {
    int tid = threadIdx.x;
    s->red[tid] = v;
    __syncthreads();
    for (int off = NTHREADS / 2; off > 0; off >>= 1) {
        if (tid < off) s->red[tid] += s->red[tid + off];
        __syncthreads();
    }
    float r = s->red[0];
    __syncthreads();
    return r;
}

__global__ void __launch_bounds__(NTHREADS, 1)
zero_kernel(float* out, int n) {
    int i = blockIdx.x * blockDim.x + threadIdx.x;
    if (i < n) out[i] = 0.0f;
}

__global__ void __launch_bounds__(NTHREADS, 1)
malis_kernel(const float* __restrict__ pred,
             const float* __restrict__ target,
             const float* __restrict__ lrn_p,
             const float* __restrict__ lrp_p,
             float* __restrict__ out,
             int HW) {
    extern __shared__ char smem_raw[];
    Smem* s = (Smem*)smem_raw;
    int tid = threadIdx.x;

    int wpr = HW / WIN;                 // windows per row (8)
    int winPerImg = wpr * wpr;          // 64
    int b  = blockIdx.x / winPerImg;
    int rem = blockIdx.x - b * winPerImg;
    int k = rem / wpr;
    int j = rem - k * wpr;
    int y0 = k * WIN, x0 = j * WIN;

    const float* pb = pred + (size_t)b * HW * HW;
    const float* tb = target + (size_t)b * HW * HW;

    // ---- load tile, build zero-mask ----
    for (int px = tid; px < NPX; px += NTHREADS) {
        int y = px >> 5, x = px & 31;
        float pv = pb[(y0 + y) * HW + (x0 + x)];
        float tv = tb[(y0 + y) * HW + (x0 + x)];
        s->pred[px] = pv;
        s->tv[px] = tv;
        s->mA[px] = (tv == 0.0f) ? 1 : 0;
    }
    __syncthreads();

    // ---- dilate 5x (4-neighborhood), window-local ----
    unsigned char* src = s->mA;
    unsigned char* dst = s->mB;
    for (int it = 0; it < 5; it++) {
        for (int px = tid; px < NPX; px += NTHREADS) {
            int y = px >> 5, x = px & 31;
            unsigned char v = src[px];
            if (y > 0)  v |= src[px - 32];
            if (y < 31) v |= src[px + 32];
            if (x > 0)  v |= src[px - 1];
            if (x < 31) v |= src[px + 1];
            dst[px] = v;
        }
        __syncthreads();
        unsigned char* t2 = src; src = dst; dst = t2;
    }
    // src = dilated mask; active region = !dilated

    // ---- 8-connected CC labeling by min-index propagation (in place) ----
    for (int px = tid; px < NPX; px += NTHREADS)
        s->lab[px] = src[px] ? 0 : (unsigned short)(px + 1);
    __syncthreads();

    for (;;) {
        if (tid == 0) s->changed = 0;
        __syncthreads();
        for (int px = tid; px < NPX; px += NTHREADS) {
            unsigned short L = s->lab[px];
            if (L) {
                int y = px >> 5, x = px & 31;
                unsigned short m = L;
                for (int dy = -1; dy <= 1; dy++) {
                    int ny = y + dy;
                    if (ny < 0 || ny > 31) continue;
                    for (int dx = -1; dx <= 1; dx++) {
                        int nx = x + dx;
                        if (nx < 0 || nx > 31) continue;
                        unsigned short nl = s->lab[(ny << 5) + nx];
                        if (nl && nl < m) m = nl;
                    }
                }
                if (m < L) { s->lab[px] = m; s->changed = 1; }
            }
        }
        __syncthreads();
        int c = s->changed;
        __syncthreads();
        if (!c) break;
    }

    // ---- per-edge flags, weight init ----
    for (int e = tid; e < NEDGE; e += NTHREADS) {
        int n1, n2;
        edge_nodes(e, n1, n2);
        float gtc = s->tv[n1] + s->tv[n2];  // exact small-int sums
        unsigned char f = 0;
        if (gtc < 10.0f)  f |= 1;   // neg weight kept; pos cost zeroed
        if (gtc >= 20.0f) f |= 2;   // pos weight kept
        if (gtc > 20.0f)  f |= 4;   // neg cost clamped to 20
        s->eflags[e] = f;
        s->w0[e] = 0.0f;
        s->w1[e] = 0.0f;
    }
    // ---- union-find init for both runs ----
    for (int px = tid; px < NPX; px += NTHREADS) {
        unsigned short L = s->lab[px];
        for (int r = 0; r < 2; r++) {
            s->parent[r][px] = (unsigned short)px;
            if (L) {
                s->tot[r][px] = 1;
                s->nent[r][px] = 1;
                s->head[r][px] = (short)px;
                s->elab[r][px] = L;
                s->ecnt[r][px] = 1;
                s->enext[r][px] = -1;
            } else {
                s->tot[r][px] = 0;
                s->nent[r][px] = 0;
                s->head[r][px] = -1;
            }
        }
    }
    __syncthreads();

    // ---- sort neg costs (descending, stable by index) ----
    for (int i = tid; i < SORTN; i += NTHREADS) {
        unsigned long long key;
        if (i < NEDGE) {
            int n1, n2;
            edge_nodes(i, n1, n2);
            float c = s->pred[n1] + s->pred[n2];
            if (s->eflags[i] & 4) c = 20.0f;
            key = (((unsigned long long)(~__float_as_uint(c))) << 32) | (unsigned)i;
        } else {
            key = 0xFFFFFFFFFFFFFFFFULL;
        }
        s->sortbuf[i] = key;
    }
    __syncthreads();
    bitonic_sort(s);
    for (int i = tid; i < NEDGE; i += NTHREADS)
        s->order0[i] = (unsigned short)(s->sortbuf[i] & 0xFFFFu);
    __syncthreads();

    // ---- sort pos costs ----
    for (int i = tid; i < SORTN; i += NTHREADS) {
        unsigned long long key;
        if (i < NEDGE) {
            float c;
            if (s->eflags[i] & 1) {
                c = 0.0f;
            } else {
                int n1, n2;
                edge_nodes(i, n1, n2);
                c = s->pred[n1] + s->pred[n2];
            }
            key = (((unsigned long long)(~__float_as_uint(c))) << 32) | (unsigned)i;
        } else {
            key = 0xFFFFFFFFFFFFFFFFULL;
        }
        s->sortbuf[i] = key;
    }
    __syncthreads();
    bitonic_sort(s);
    for (int i = tid; i < NEDGE; i += NTHREADS)
        s->order1[i] = (unsigned short)(s->sortbuf[i] & 0xFFFFu);
    __syncthreads();

    // ---- two concurrent serial Kruskal runs (different warps) ----
    if (tid == 0)        kruskal(s, 0, s->order0, false);
    else if (tid == 128) kruskal(s, 1, s->order1, true);
    __syncthreads();

    // ---- normalize by total, then mask ----
    float vn = 0.0f, vp = 0.0f;
    for (int e = tid; e < NEDGE; e += NTHREADS) {
        vn += s->w0[e];
        vp += s->w1[e];
    }
    float sn = block_reduce(s, vn);
    float sp = block_reduce(s, vp);

    for (int e = tid; e < NEDGE; e += NTHREADS) {
        unsigned char f = s->eflags[e];
        float a = s->w0[e];
        if (sn > 0.0f) a /= sn;
        s->w0[e] = (f & 1) ? a : 0.0f;
        float bb = s->w1[e];
        if (sp > 0.0f) bb /= sp;
        s->w1[e] = (f & 2) ? bb : 0.0f;
    }
    __syncthreads();

    // ---- gather edge weights to nodes, compute loss ----
    float lrn = lrn_p[0];
    float lrp = lrp_p[0];
    float acc = 0.0f;
    for (int px = tid; px < NPX; px += NTHREADS) {
        int y = px >> 5, x = px & 31;
        float wn = 0.0f, wp = 0.0f;
        if (x > 0)  { int e = y * 31 + x - 1; wn += s->w0[e]; wp += s->w1[e]; }
        if (x < 31) { int e = y * 31 + x;     wn += s->w0[e]; wp += s->w1[e]; }
        if (y > 0)  { int e = NH + px - 32;   wn += s->w0[e]; wp += s->w1[e]; }
        if (y < 31) { int e = NH + px;        wn += s->w0[e]; wp += s->w1[e]; }
        float p = s->pred[px];
        float d = 20.0f - p;
        acc += lrn * p * p * wn + lrp * d * d * wp;
    }
    float total = block_reduce(s, acc);
    if (tid == 0) atomicAdd(out, total);
}

extern "C" void kernel_launch(void* const* d_in, const int* in_sizes, int n_in,
                              void* d_out, int out_size) {
    const float* pred   = (const float*)d_in[0];
    const float* target = (const float*)d_in[1];
    const float* lrn    = (const float*)d_in[2];
    const float* lrp    = (const float*)d_in[3];
    float* out = (float*)d_out;

    const int HW = 256;
    int B = in_sizes[0] / (HW * HW);
    int nblocks = B * (HW / WIN) * (HW / WIN);

    cudaFuncSetAttribute(malis_kernel,
                         cudaFuncAttributeMaxDynamicSharedMemorySize,
                         (int)sizeof(Smem));

    zero_kernel<<<(out_size + NTHREADS - 1) / NTHREADS, NTHREADS>>>(out, out_size);
    malis_kernel<<<nblocks, NTHREADS, sizeof(Smem)>>>(pred, target, lrn, lrp, out, HW);
}

// round 2
// speedup vs baseline: 1.4710x; 1.4710x over previous
#include <cuda_runtime.h>
#include <stdint.h>

#define WIN 32
#define NPX 1024
#define NH 992
#define NEDGE 1984
#define SORTN 2048
#define NTHREADS 256
#define FULLM 0xffffffffu

#define BARSYNC(id) asm volatile("bar.sync %0, %1;" :: "r"(id), "r"(128) : "memory")

struct Smem {
    float pred[NPX];
    unsigned char tvi[NPX];
    unsigned char mA[NPX];
    unsigned char mB[NPX];
    unsigned short lab[NPX];
    unsigned char pres[NPX];
    unsigned short cid[NPX];
    unsigned char eflags[NEDGE];
    float w0[NEDGE];
    float w1[NEDGE];
    unsigned short order0[NEDGE];
    unsigned short order1[NEDGE];
    unsigned short parent[2][NPX];
    unsigned short siz[2][NPX];   // union-by-size (all nodes)
    unsigned short tot[2][NPX];   // labeled-pixel count per component
    unsigned short logE[2][NPX];
    unsigned short logRS[2][NPX];
    unsigned short logRL[2][NPX];
    unsigned short logSA[2][NPX]; // tot[rs] at merge
    unsigned short logSB[2][NPX]; // tot[rl] at merge
    int Lval;
    int changed;
    int wsum[8];
    int wpre[8];
    float red[NTHREADS];
    // big[r]: during sorts = u64 sortbuf (16KB used of 64KB);
    // during replay = u16 cnt[NPX][32] (64KB)
    alignas(16) unsigned char big[2][65536];
};

__device__ __forceinline__ void edge_nodes(int e, int& n1, int& n2) {
    if (e < NH) {
        int r = e / 31;
        int c = e - r * 31;
        n1 = (r << 5) + c;
        n2 = n1 + 1;
    } else {
        n1 = e - NH;
        n2 = n1 + 32;
    }
}

// Path-halving find. Safe under concurrent same-structure use within a warp:
// every write moves parent[x] to an ancestor of x.
__device__ __forceinline__ int uf_find(unsigned short* par, int x) {
    while (par[x] != x) {
        par[x] = par[par[x]];
        x = par[x];
    }
    return x;
}

// Bitonic sort over SORTN u64 keys with 128 threads; named barrier barid.
__device__ void bitonic_sort_half(unsigned long long* buf, int t, int barid) {
    for (int k = 2; k <= SORTN; k <<= 1) {
        for (int jj = k >> 1; jj > 0; jj >>= 1) {
            for (int i = t; i < SORTN; i += 128) {
                int p = i ^ jj;
                if (p > i) {
                    unsigned long long a = buf[i];
                    unsigned long long b = buf[p];
                    bool up = ((i & k) == 0);
                    if ((a > b) == up) { buf[i] = b; buf[p] = a; }
                }
            }
            BARSYNC(barid);
        }
    }
}

// Warp-cooperative speculative Kruskal. Returns number of logged merges.
// Executed in lockstep by one full warp. Pure union-find + merge log; no
// label-count work here. Weights depend only on the partition sequence, so
// union direction is free (we use union-by-size for shallow trees).
__device__ int kruskal_warp(Smem* s, int run, const unsigned short* order) {
    unsigned short* par = s->parent[run];
    unsigned short* siz = s->siz[run];
    unsigned short* tot = s->tot[run];
    unsigned short* lE  = s->logE[run];
    unsigned short* lRS = s->logRS[run];
    unsigned short* lRL = s->logRL[run];
    unsigned short* lSA = s->logSA[run];
    unsigned short* lSB = s->logSB[run];

    const int lane = threadIdx.x & 31;
    int nlog = 0;
    unsigned myMerged = 0xffffffffu;

    for (int base = 0; base < NEDGE; base += 32) {
        int e = order[base + lane];
        int n1, n2;
        edge_nodes(e, n1, n2);
        int ra = uf_find(par, n1);
        int rb = uf_find(par, n2);
        __syncwarp();
        // "connected in snapshot" is monotone => safe to drop those edges.
        unsigned alive = __ballot_sync(FULLM, ra != rb);
        int m = 0; // merges in this batch; lanes [0,m) hold merged rs values
        while (alive) {
            int i = __ffs(alive) - 1;
            alive &= alive - 1;
            int rai = __shfl_sync(FULLM, ra, i);
            int rbi = __shfl_sync(FULLM, rb, i);
            int ei  = __shfl_sync(FULLM, e,  i);
            // Only rs nodes lose rootness; components merge only via logged
            // unions, so checking stale roots against the batch rs-set is
            // sufficient to detect invalidation.
            bool touched = (lane < m) &&
                           (myMerged == (unsigned)rai || myMerged == (unsigned)rbi);
            if (__any_sync(FULLM, touched)) {
                rai = uf_find(par, rai);   // short chains; all lanes redundant
                rbi = uf_find(par, rbi);
                if (rai == rbi) continue;
            }
            int sza = siz[rai], szb = siz[rbi];
            int rs, rl;
            if (sza <= szb) { rs = rai; rl = rbi; }
            else            { rs = rbi; rl = rai; }
            int sa = tot[rs], sb = tot[rl];
            // all lanes store identical values: write-collapse, well-defined
            par[rs] = (unsigned short)rl;
            siz[rl] = (unsigned short)(sza + szb);
            tot[rl] = (unsigned short)(sa + sb);
            lE[nlog]  = (unsigned short)ei;
            lRS[nlog] = (unsigned short)rs;
            lRL[nlog] = (unsigned short)rl;
            lSA[nlog] = (unsigned short)sa;
            lSB[nlog] = (unsigned short)sb;
            if (lane == m) myMerged = (unsigned)rs;
            m++;
            nlog++;
        }
        __syncwarp();
    }
    return nlog;
}

// Warp-vectorized count replay: lane = compact label id (chunk of 32 per pass).
__device__ void replay_warp(Smem* s, int run, int nlog, int L, bool pos) {
    const int lane = threadIdx.x & 31;
    unsigned short (*cnt)[32] = (unsigned short(*)[32])(s->big[run]);
    float* w = pos ? s->w1 : s->w0;

    for (int p = 0; p * 32 < L; p++) {
        if (p > 0) {
            unsigned* c32 = (unsigned*)cnt;
            for (int i = lane; i < NPX * 16; i += 32) c32[i] = 0;
            __syncwarp();
            for (int px = lane; px < NPX; px += 32) {
                int l = s->lab[px];
                if (l) {
                    int c = (int)s->cid[l - 1] - p * 32;
                    if (c >= 0 && c < 32) cnt[px][c] = 1;
                }
            }
            __syncwarp();
        }
        for (int k = 0; k < nlog; k++) {
            int sa = s->logSA[run][k];  // labeled count in rs
            int sb = s->logSB[run][k];  // labeled count in rl
            if (sa == 0) continue;      // rs row all-zero: no-op, weight 0
            int rs = s->logRS[run][k];
            int rl = s->logRL[run][k];
            if (sb == 0) {              // copy rs row into rl; weight 0
                cnt[rl][lane] = cnt[rs][lane];
                continue;
            }
            unsigned a = cnt[rs][lane];
            unsigned b = cnt[rl][lane];
            unsigned same = __reduce_add_sync(FULLM, a * b);
            cnt[rl][lane] = (unsigned short)(a + b);
            if (lane == 0) {
                int e = s->logE[run][k];
                if (pos) {
                    w[e] += (float)same;
                } else {
                    if (p == 0) w[e] = (float)(sa * sb) - (float)same;
                    else        w[e] -= (float)same;
                }
            }
        }
        __syncwarp();
    }
}

__device__ float block_reduce(Smem* s, float v) {
    int tid = threadIdx.x;
    s->red[tid] = v;
    __syncthreads();
    for (int off = NTHREADS / 2; off > 0; off >>= 1) {
        if (tid < off) s->red[tid] += s->red[tid + off];
        __syncthreads();
    }
    float r = s->red[0];
    __syncthreads();
    return r;
}

__global__ void __launch_bounds__(NTHREADS, 1)
zero_kernel(float* out, int n) {
    int i = blockIdx.x * blockDim.x + threadIdx.x;
    if (i < n) out[i] = 0.0f;
}

__global__ void __launch_bounds__(NTHREADS, 1)
malis_kernel(const float* __restrict__ pred,
             const float* __restrict__ target,
             const float* __restrict__ lrn_p,
             const float* __restrict__ lrp_p,
             float* __restrict__ out,
             int HW) {
    extern __shared__ char smem_raw[];
    Smem* s = (Smem*)smem_raw;
    const int tid = threadIdx.x;
    const int lane = tid & 31;

    int wpr = HW / WIN;
    int winPerImg = wpr * wpr;
    int b = blockIdx.x / winPerImg;
    int rem = blockIdx.x - b * winPerImg;
    int k = rem / wpr;
    int j = rem - k * wpr;
    int y0 = k * WIN, x0 = j * WIN;

    const float* pb = pred + (size_t)b * HW * HW;
    const float* tb = target + (size_t)b * HW * HW;

    // ---- 1. load tile ----
    for (int px = tid; px < NPX; px += NTHREADS) {
        int y = px >> 5, x = px & 31;
        float pv = pb[(y0 + y) * HW + (x0 + x)];
        float tv = tb[(y0 + y) * HW + (x0 + x)];
        s->pred[px] = pv;
        s->tvi[px] = (unsigned char)tv;       // ints 0..25, exact
        s->mA[px] = (tv == 0.0f) ? 1 : 0;
    }
    __syncthreads();

    // ---- 2. dilate 5x (4-neighborhood, window-local) ----
    unsigned char* src = s->mA;
    unsigned char* dst = s->mB;
    for (int it = 0; it < 5; it++) {
        for (int px = tid; px < NPX; px += NTHREADS) {
            int y = px >> 5, x = px & 31;
            unsigned char v = src[px];
            if (y > 0)  v |= src[px - 32];
            if (y < 31) v |= src[px + 32];
            if (x > 0)  v |= src[px - 1];
            if (x < 31) v |= src[px + 1];
            dst[px] = v;
        }
        __syncthreads();
        unsigned char* t2 = src; src = dst; dst = t2;
    }

    // ---- 3. 8-connected CC labels by min-index propagation ----
    for (int px = tid; px < NPX; px += NTHREADS)
        s->lab[px] = src[px] ? 0 : (unsigned short)(px + 1);
    __syncthreads();
    for (;;) {
        if (tid == 0) s->changed = 0;
        __syncthreads();
        for (int px = tid; px < NPX; px += NTHREADS) {
            unsigned short L = s->lab[px];
            if (L) {
                int y = px >> 5, x = px & 31;
                unsigned short mm = L;
                for (int dy = -1; dy <= 1; dy++) {
                    int ny = y + dy;
                    if (ny < 0 || ny > 31) continue;
                    for (int dx = -1; dx <= 1; dx++) {
                        int nx = x + dx;
                        if (nx < 0 || nx > 31) continue;
                        unsigned short nl = s->lab[(ny << 5) + nx];
                        if (nl && nl < mm) mm = nl;
                    }
                }
                if (mm < L) { s->lab[px] = mm; s->changed = 1; }
            }
        }
        __syncthreads();
        int c = s->changed;
        __syncthreads();
        if (!c) break;
    }

    // ---- 4. compact label ids (presence -> exclusive scan -> cid) ----
    for (int px = tid; px < NPX; px += NTHREADS) s->pres[px] = 0;
    __syncthreads();
    for (int px = tid; px < NPX; px += NTHREADS) {
        int l = s->lab[px];
        if (l) s->pres[l - 1] = 1;
    }
    __syncthreads();
    {
        int i0 = 4 * tid;
        int b0 = s->pres[i0], b1 = s->pres[i0 + 1];
        int b2 = s->pres[i0 + 2], b3 = s->pres[i0 + 3];
        int sum4 = b0 + b1 + b2 + b3;
        int incl = sum4;
        for (int off = 1; off < 32; off <<= 1) {
            int v = __shfl_up_sync(FULLM, incl, off);
            if (lane >= off) incl += v;
        }
        if (lane == 31) s->wsum[tid >> 5] = incl;
        __syncthreads();
        if (tid < 8) {
            int v = s->wsum[tid];
            int inc2 = v;
            for (int off = 1; off < 8; off <<= 1) {
                int t2 = __shfl_up_sync(0xffu, inc2, off);
                if (tid >= off) inc2 += t2;
            }
            s->wpre[tid] = inc2 - v;
            if (tid == 7) s->Lval = inc2;
        }
        __syncthreads();
        int pre = s->wpre[tid >> 5] + (incl - sum4);
        s->cid[i0]     = (unsigned short)pre;
        s->cid[i0 + 1] = (unsigned short)(pre + b0);
        s->cid[i0 + 2] = (unsigned short)(pre + b0 + b1);
        s->cid[i0 + 3] = (unsigned short)(pre + b0 + b1 + b2);
    }

    // ---- 5. edge flags, weight init, union-find init ----
    for (int e = tid; e < NEDGE; e += NTHREADS) {
        int n1, n2;
        edge_nodes(e, n1, n2);
        int gtc = (int)s->tvi[n1] + (int)s->tvi[n2];  // exact
        unsigned char f = 0;
        if (gtc < 10)  f |= 1;  // neg weight kept; pos cost zeroed
        if (gtc >= 20) f |= 2;  // pos weight kept
        if (gtc > 20)  f |= 4;  // neg cost clamped to 20
        s->eflags[e] = f;
        s->w0[e] = 0.0f;
        s->w1[e] = 0.0f;
    }
    for (int px = tid; px < NPX; px += NTHREADS) {
        unsigned short L = s->lab[px];
        for (int r = 0; r < 2; r++) {
            s->parent[r][px] = (unsigned short)px;
            s->siz[r][px] = 1;
            s->tot[r][px] = L ? 1 : 0;
        }
    }
    __syncthreads();

    // ---- 6. two concurrent bitonic sorts (half-block each) ----
    {
        int half = tid >> 7;          // 0: neg costs, 1: pos costs
        int t128 = tid & 127;
        int barid = half + 1;
        unsigned long long* sb = (unsigned long long*)(s->big[half]);
        for (int i = t128; i < SORTN; i += 128) {
            unsigned long long key;
            if (i < NEDGE) {
                int n1, n2;
                edge_nodes(i, n1, n2);
                float c;
                if (half == 0) {
                    c = s->pred[n1] + s->pred[n2];
                    if (s->eflags[i] & 4) c = 20.0f;
                } else {
                    c = (s->eflags[i] & 1) ? 0.0f
                                           : s->pred[n1] + s->pred[n2];
                }
                // nonneg floats: bit pattern is order-monotone.
                // ascending u64 = descending cost, ties by ascending index.
                key = (((unsigned long long)(~__float_as_uint(c))) << 32)
                      | (unsigned)i;
            } else {
                key = ~0ULL;
            }
            sb[i] = key;
        }
        BARSYNC(barid);
        bitonic_sort_half(sb, t128, barid);
        unsigned short* ord = half ? s->order1 : s->order0;
        for (int i = t128; i < NEDGE; i += 128)
            ord[i] = (unsigned short)(sb[i] & 0xffffu);
    }
    __syncthreads();

    // ---- 7. zero cnt matrices (alias sortbuf) + scatter labeled pixels ----
    {
        unsigned* c32 = (unsigned*)s->big;
        for (int i = tid; i < 2 * 65536 / 4; i += NTHREADS) c32[i] = 0;
    }
    __syncthreads();
    {
        unsigned short (*c0)[32] = (unsigned short(*)[32])(s->big[0]);
        unsigned short (*c1)[32] = (unsigned short(*)[32])(s->big[1]);
        for (int px = tid; px < NPX; px += NTHREADS) {
            int l = s->lab[px];
            if (l) {
                int c = s->cid[l - 1];
                if (c < 32) { c0[px][c] = 1; c1[px][c] = 1; }
            }
        }
    }
    __syncthreads();

    // ---- 8. concurrent Kruskal + replay: warp 0 = neg, warp 4 = pos ----
    {
        int wid = tid >> 5;
        int L = s->Lval;
        if (wid == 0) {
            int nlog = kruskal_warp(s, 0, s->order0);
            replay_warp(s, 0, nlog, L, false);
        } else if (wid == 4) {
            int nlog = kruskal_warp(s, 1, s->order1);
            replay_warp(s, 1, nlog, L, true);
        }
    }
    __syncthreads();

    // ---- 9. normalize, mask, gather to nodes, loss ----
    float vn = 0.0f, vp = 0.0f;
    for (int e = tid; e < NEDGE; e += NTHREADS) {
        vn += s->w0[e];
        vp += s->w1[e];
    }
    float sn = block_reduce(s, vn);
    float sp = block_reduce(s, vp);

    for (int e = tid; e < NEDGE; e += NTHREADS) {
        unsigned char f = s->eflags[e];
        float a = s->w0[e];
        if (sn > 0.0f) a /= sn;
        s->w0[e] = (f & 1) ? a : 0.0f;
        float bb = s->w1[e];
        if (sp > 0.0f) bb /= sp;
        s->w1[e] = (f & 2) ? bb : 0.0f;
    }
    __syncthreads();

    float lrn = lrn_p[0];
    float lrp = lrp_p[0];
    float acc = 0.0f;
    for (int px = tid; px < NPX; px += NTHREADS) {
        int y = px >> 5, x = px & 31;
        float wn = 0.0f, wp = 0.0f;
        if (x > 0)  { int e = y * 31 + x - 1; wn += s->w0[e]; wp += s->w1[e]; }
        if (x < 31) { int e = y * 31 + x;     wn += s->w0[e]; wp += s->w1[e]; }
        if (y > 0)  { int e = NH + px - 32;   wn += s->w0[e]; wp += s->w1[e]; }
        if (y < 31) { int e = NH + px;        wn += s->w0[e]; wp += s->w1[e]; }
        float p = s->pred[px];
        float d = 20.0f - p;
        acc += lrn * p * p * wn + lrp * d * d * wp;
    }
    float total = block_reduce(s, acc);
    if (tid == 0) atomicAdd(out, total);
}

extern "C" void kernel_launch(void* const* d_in, const int* in_sizes, int n_in,
                              void* d_out, int out_size) {
    const float* pred   = (const float*)d_in[0];
    const float* target = (const float*)d_in[1];
    const float* lrn    = (const float*)d_in[2];
    const float* lrp    = (const float*)d_in[3];
    float* out = (float*)d_out;

    const int HW = 256;
    int B = in_sizes[0] / (HW * HW);
    int nblocks = B * (HW / WIN) * (HW / WIN);

    cudaFuncSetAttribute(malis_kernel,
                         cudaFuncAttributeMaxDynamicSharedMemorySize,
                         (int)sizeof(Smem));

    zero_kernel<<<(out_size + NTHREADS - 1) / NTHREADS, NTHREADS>>>(out, out_size);
    malis_kernel<<<nblocks, NTHREADS, sizeof(Smem)>>>(pred, target, lrn, lrp, out, HW);
}

// round 7
// speedup vs baseline: 1.7957x; 1.2207x over previous
#include <cuda_runtime.h>
#include <stdint.h>

#define WIN 32
#define NPX 1024
#define NH 992
#define NEDGE 1984
#define SORTN 2048
#define NTHREADS 256
#define FULLM 0xffffffffu
#define DONE_BIT (1 << 30)

#define BARSYNC(id) asm volatile("bar.sync %0, %1;" :: "r"(id), "r"(128) : "memory")

struct Smem {
    float pred[NPX];
    unsigned char tvi[NPX];
    unsigned rowmask[32];          // dilated mask bits, 1 = masked
    unsigned par32[NPX];           // CC labeling union-find (u32 for atomicCAS)
    unsigned short lab[NPX];
    unsigned char pres[NPX];
    unsigned short cid[NPX];
    unsigned char eflags[NEDGE];
    float w0[NEDGE];
    float w1[NEDGE];
    unsigned short order0[NEDGE];
    unsigned short order1[NEDGE];
    unsigned short parent[2][NPX];
    unsigned short siz[2][NPX];    // union-by-size
    unsigned short tot[2][NPX];    // labeled-pixel count per component
    unsigned short logE[2][NPX];
    unsigned short logRS[2][NPX];
    unsigned short logRL[2][NPX];
    unsigned short logSA[2][NPX];
    unsigned short logSB[2][NPX];
    int logCnt[2];
    int Lval;
    int wsum[8];
    int wpre[8];
    float red[NTHREADS];
    // big[r]: sorts = u64 sortbuf (16KB of 64KB); replay = u16 cnt[NPX][32]
    alignas(16) unsigned char big[2][65536];
};

__device__ __forceinline__ void edge_nodes(int e, int& n1, int& n2) {
    if (e < NH) {
        int r = e / 31;
        int c = e - r * 31;
        n1 = (r << 5) + c;
        n2 = n1 + 1;
    } else {
        n1 = e - NH;
        n2 = n1 + 32;
    }
}

__device__ __forceinline__ int uf_find(unsigned short* par, int x) {
    while (par[x] != x) {
        par[x] = par[par[x]];
        x = par[x];
    }
    return x;
}

// ---- lock-free CC union-find (shared mem) ----
// Path-halving find: writes only par[x] = grandparent(x), NEVER writes to a
// root, so committed unions can never be resurrected by a racing find.
// Invariant par[x] <= x (attach larger under smaller) => x strictly
// decreases => termination. volatile reads stop register-caching.
__device__ __forceinline__ unsigned cc_find(unsigned* par_, unsigned x) {
    volatile unsigned* par = par_;
    for (;;) {
        unsigned p = par[x];
        if (p == x) return x;
        unsigned g = par[p];
        if (g == p) return p;      // p is root
        par[x] = g;                // halve (g is an ancestor, g < x)
        x = g;
    }
}

// Attach larger root under smaller root via CAS; retry on races.
// Global progress: every failed CAS implies another union committed, and
// path-halving never undoes a union => no livelock.
__device__ __forceinline__ void cc_union(unsigned* par, unsigned a, unsigned b) {
    a = cc_find(par, a);
    b = cc_find(par, b);
    while (a != b) {
        if (a < b) { unsigned t = a; a = b; b = t; }   // ensure a > b
        unsigned old = atomicCAS(&par[a], a, b);
        if (old == a) return;                          // linked a under b
        a = cc_find(par, old);                         // a moved; re-resolve
        b = cc_find(par, b);
    }
}

// Bitonic sort over SORTN u64 keys with 128 threads; named barrier barid.
__device__ void bitonic_sort_half(unsigned long long* buf, int t, int barid) {
    for (int k = 2; k <= SORTN; k <<= 1) {
        for (int jj = k >> 1; jj > 0; jj >>= 1) {
            for (int i = t; i < SORTN; i += 128) {
                int p = i ^ jj;
                if (p > i) {
                    unsigned long long a = buf[i];
                    unsigned long long b = buf[p];
                    bool up = ((i & k) == 0);
                    if ((a > b) == up) { buf[i] = b; buf[p] = a; }
                }
            }
            BARSYNC(barid);
        }
    }
}

// Warp-cooperative speculative Kruskal (producer). Streams merge log entries
// and publishes progress per batch via logCnt (release: fence + volatile store).
__device__ void kruskal_warp(Smem* s, int run, const unsigned short* order) {
    unsigned short* par = s->parent[run];
    unsigned short* siz = s->siz[run];
    unsigned short* tot = s->tot[run];
    unsigned short* lE  = s->logE[run];
    unsigned short* lRS = s->logRS[run];
    unsigned short* lRL = s->logRL[run];
    unsigned short* lSA = s->logSA[run];
    unsigned short* lSB = s->logSB[run];
    volatile int* vc = &s->logCnt[run];

    const int lane = threadIdx.x & 31;
    int nlog = 0;
    unsigned myMerged = 0xffffffffu;

    for (int base = 0; base < NEDGE; base += 32) {
        int e = order[base + lane];
        int n1, n2;
        edge_nodes(e, n1, n2);
        int ra = uf_find(par, n1);
        int rb = uf_find(par, n2);
        __syncwarp();
        // "connected in snapshot" is monotone => safe to drop those edges.
        unsigned alive = __ballot_sync(FULLM, ra != rb);
        int m = 0;  // merges this batch; lanes [0,m) hold merged rs values
        while (alive) {
            int i = __ffs(alive) - 1;
            alive &= alive - 1;
            int rai = __shfl_sync(FULLM, ra, i);
            int rbi = __shfl_sync(FULLM, rb, i);
            int ei  = __shfl_sync(FULLM, e,  i);
            // Only rs nodes lose rootness; stale roots must be in this
            // batch's rs-set, so a ballot check suffices.
            bool touched = (lane < m) &&
                           (myMerged == (unsigned)rai || myMerged == (unsigned)rbi);
            if (__any_sync(FULLM, touched)) {
                rai = uf_find(par, rai);
                rbi = uf_find(par, rbi);
                if (rai == rbi) continue;
            }
            int sza = siz[rai], szb = siz[rbi];
            int rs, rl;
            if (sza <= szb) { rs = rai; rl = rbi; }
            else            { rs = rbi; rl = rai; }
            int sa = tot[rs], sb = tot[rl];
            par[rs] = (unsigned short)rl;   // all lanes store same value
            siz[rl] = (unsigned short)(sza + szb);
            tot[rl] = (unsigned short)(sa + sb);
            lE[nlog]  = (unsigned short)ei;
            lRS[nlog] = (unsigned short)rs;
            lRL[nlog] = (unsigned short)rl;
            lSA[nlog] = (unsigned short)sa;
            lSB[nlog] = (unsigned short)sb;
            if (lane == m) myMerged = (unsigned)rs;
            m++;
            nlog++;
        }
        if (lane == 0 && m > 0) {
            __threadfence_block();
            *vc = nlog;
        }
        __syncwarp();
    }
    if (lane == 0) {
        __threadfence_block();
        *vc = nlog | DONE_BIT;
    }
}

// Streaming replay consumer (pass 0) + extra passes for L > 32.
__device__ void replay_consumer(Smem* s, int run, int L, bool pos) {
    const int lane = threadIdx.x & 31;
    unsigned short (*cnt)[32] = (unsigned short(*)[32])(s->big[run]);
    float* w = pos ? s->w1 : s->w0;
    volatile int* vc = &s->logCnt[run];

    int processed = 0, avail = 0;
    bool done = false;
    int nlog = 0;
    for (;;) {
        if (processed >= avail) {
            if (done) break;
            int v = *vc;                 // broadcast LDS
            int na = v & ~DONE_BIT;
            if (v & DONE_BIT) { done = true; nlog = na; }
            if (na > avail) {
                avail = na;
                __threadfence_block();   // acquire: order log reads after count
            }
            if (processed >= avail) {
                if (done) break;
                continue;
            }
        }
        int k = processed++;
        int sa = s->logSA[run][k];
        int sb = s->logSB[run][k];
        if (sa == 0) continue;
        int rs = s->logRS[run][k];
        int rl = s->logRL[run][k];
        if (sb == 0) { cnt[rl][lane] = cnt[rs][lane]; continue; }
        unsigned a = cnt[rs][lane];
        unsigned b = cnt[rl][lane];
        unsigned same = __reduce_add_sync(FULLM, a * b);
        cnt[rl][lane] = (unsigned short)(a + b);
        if (lane == 0) {
            int e = s->logE[run][k];
            w[e] = pos ? (float)same : (float)(sa * sb) - (float)same;
        }
    }

    // extra label chunks (rare: L > 32)
    for (int p = 1; p * 32 < L; p++) {
        unsigned* c32 = (unsigned*)cnt;
        for (int i = lane; i < NPX * 16; i += 32) c32[i] = 0;
        __syncwarp();
        for (int px = lane; px < NPX; px += 32) {
            int l = s->lab[px];
            if (l) {
                int c = (int)s->cid[l - 1] - p * 32;
                if (c >= 0 && c < 32) cnt[px][c] = 1;
            }
        }
        __syncwarp();
        for (int k = 0; k < nlog; k++) {
            int sa = s->logSA[run][k];
            int sb = s->logSB[run][k];
            if (sa == 0) continue;
            int rs = s->logRS[run][k];
            int rl = s->logRL[run][k];
            if (sb == 0) { cnt[rl][lane] = cnt[rs][lane]; continue; }
            unsigned a = cnt[rs][lane];
            unsigned b = cnt[rl][lane];
            unsigned same = __reduce_add_sync(FULLM, a * b);
            cnt[rl][lane] = (unsigned short)(a + b);
            if (lane == 0) {
                int e = s->logE[run][k];
                if (pos) w[e] += (float)same;
                else     w[e] -= (float)same;
            }
        }
        __syncwarp();
    }
}

__device__ float block_reduce(Smem* s, float v) {
    int tid = threadIdx.x;
    s->red[tid] = v;
    __syncthreads();
    for (int off = NTHREADS / 2; off > 0; off >>= 1) {
        if (tid < off) s->red[tid] += s->red[tid + off];
        __syncthreads();
    }
    float r = s->red[0];
    __syncthreads();
    return r;
}

__global__ void __launch_bounds__(NTHREADS, 1)
zero_kernel(float* out, int n) {
    int i = blockIdx.x * blockDim.x + threadIdx.x;
    if (i < n) out[i] = 0.0f;
}

__global__ void __launch_bounds__(NTHREADS, 1)
malis_kernel(const float* __restrict__ pred,
             const float* __restrict__ target,
             const float* __restrict__ lrn_p,
             const float* __restrict__ lrp_p,
             float* __restrict__ out,
             int HW) {
    extern __shared__ char smem_raw[];
    Smem* s = (Smem*)smem_raw;
    const int tid = threadIdx.x;
    const int lane = tid & 31;

    int wpr = HW / WIN;
    int winPerImg = wpr * wpr;
    int b = blockIdx.x / winPerImg;
    int rem = blockIdx.x - b * winPerImg;
    int k = rem / wpr;
    int j = rem - k * wpr;
    int y0 = k * WIN, x0 = j * WIN;

    const float* pb = pred + (size_t)b * HW * HW;
    const float* tb = target + (size_t)b * HW * HW;

    // ---- 1. load tile; build zero-mask row bits via ballot ----
    for (int px = tid; px < NPX; px += NTHREADS) {
        int y = px >> 5, x = px & 31;
        float pv = pb[(y0 + y) * HW + (x0 + x)];
        float tv = tb[(y0 + y) * HW + (x0 + x)];
        s->pred[px] = pv;
        s->tvi[px] = (unsigned char)tv;            // ints 0..25, exact
        unsigned zb = __ballot_sync(FULLM, tv == 0.0f);
        if (lane == 0) s->rowmask[y] = zb;         // stride 256 => lane == x
    }
    __syncthreads();

    // ---- 2. dilate 5x in registers (warp 0, shfl across rows) ----
    if (tid < 32) {
        unsigned r = s->rowmask[tid];
        for (int it = 0; it < 5; it++) {
            unsigned up = __shfl_up_sync(FULLM, r, 1);
            unsigned dn = __shfl_down_sync(FULLM, r, 1);
            if (tid == 0) up = 0;
            if (tid == 31) dn = 0;
            r = r | (r << 1) | (r >> 1) | up | dn;
        }
        s->rowmask[tid] = r;
    }
    // init CC parents (no dependence on rowmask)
    for (int px = tid; px < NPX; px += NTHREADS) s->par32[px] = (unsigned)px;
    __syncthreads();

    // ---- 3. 8-connected CC via lock-free union-find ----
    for (int px = tid; px < NPX; px += NTHREADS) {
        int y = px >> 5, x = px & 31;
        unsigned my = s->rowmask[y];
        if ((my >> x) & 1) continue;               // masked
        if (x < 31 && !((my >> (x + 1)) & 1)) cc_union(s->par32, px, px + 1);
        if (y < 31) {
            unsigned nx = s->rowmask[y + 1];
            if (!((nx >> x) & 1))                 cc_union(s->par32, px, px + 32);
            if (x < 31 && !((nx >> (x + 1)) & 1)) cc_union(s->par32, px, px + 33);
            if (x > 0  && !((nx >> (x - 1)) & 1)) cc_union(s->par32, px, px + 31);
        }
    }
    __syncthreads();
    for (int px = tid; px < NPX; px += NTHREADS) {
        int y = px >> 5, x = px & 31;
        unsigned my = s->rowmask[y];
        s->lab[px] = ((my >> x) & 1) ? 0
                   : (unsigned short)(cc_find(s->par32, px) + 1);
    }
    __syncthreads();

    // ---- 4. compact label ids ----
    for (int px = tid; px < NPX; px += NTHREADS) s->pres[px] = 0;
    __syncthreads();
    for (int px = tid; px < NPX; px += NTHREADS) {
        int l = s->lab[px];
        if (l) s->pres[l - 1] = 1;
    }
    __syncthreads();
    {
        int i0 = 4 * tid;
        int b0 = s->pres[i0], b1 = s->pres[i0 + 1];
        int b2 = s->pres[i0 + 2], b3 = s->pres[i0 + 3];
        int sum4 = b0 + b1 + b2 + b3;
        int incl = sum4;
        for (int off = 1; off < 32; off <<= 1) {
            int v = __shfl_up_sync(FULLM, incl, off);
            if (lane >= off) incl += v;
        }
        if (lane == 31) s->wsum[tid >> 5] = incl;
        __syncthreads();
        if (tid < 8) {
            int v = s->wsum[tid];
            int inc2 = v;
            for (int off = 1; off < 8; off <<= 1) {
                int t2 = __shfl_up_sync(0xffu, inc2, off);
                if (tid >= off) inc2 += t2;
            }
            s->wpre[tid] = inc2 - v;
            if (tid == 7) s->Lval = inc2;
        }
        __syncthreads();
        int pre = s->wpre[tid >> 5] + (incl - sum4);
        s->cid[i0]     = (unsigned short)pre;
        s->cid[i0 + 1] = (unsigned short)(pre + b0);
        s->cid[i0 + 2] = (unsigned short)(pre + b0 + b1);
        s->cid[i0 + 3] = (unsigned short)(pre + b0 + b1 + b2);
    }

    // ---- 5. edge flags, weight init, Kruskal union-find init ----
    for (int e = tid; e < NEDGE; e += NTHREADS) {
        int n1, n2;
        edge_nodes(e, n1, n2);
        int gtc = (int)s->tvi[n1] + (int)s->tvi[n2];
        unsigned char f = 0;
        if (gtc < 10)  f |= 1;
        if (gtc >= 20) f |= 2;
        if (gtc > 20)  f |= 4;
        s->eflags[e] = f;
        s->w0[e] = 0.0f;
        s->w1[e] = 0.0f;
    }
    for (int px = tid; px < NPX; px += NTHREADS) {
        unsigned short L = s->lab[px];
        for (int r = 0; r < 2; r++) {
            s->parent[r][px] = (unsigned short)px;
            s->siz[r][px] = 1;
            s->tot[r][px] = L ? 1 : 0;
        }
    }
    if (tid < 2) s->logCnt[tid] = 0;
    __syncthreads();

    // ---- 6. two concurrent bitonic sorts (half-block each) ----
    {
        int half = tid >> 7;
        int t128 = tid & 127;
        int barid = half + 1;
        unsigned long long* sb = (unsigned long long*)(s->big[half]);
        for (int i = t128; i < SORTN; i += 128) {
            unsigned long long key;
            if (i < NEDGE) {
                int n1, n2;
                edge_nodes(i, n1, n2);
                float c;
                if (half == 0) {
                    c = s->pred[n1] + s->pred[n2];
                    if (s->eflags[i] & 4) c = 20.0f;
                } else {
                    c = (s->eflags[i] & 1) ? 0.0f
                                           : s->pred[n1] + s->pred[n2];
                }
                // nonneg floats: bit-monotone; ascending u64 =
                // descending cost, ties by ascending index.
                key = (((unsigned long long)(~__float_as_uint(c))) << 32)
                      | (unsigned)i;
            } else {
                key = ~0ULL;
            }
            sb[i] = key;
        }
        BARSYNC(barid);
        bitonic_sort_half(sb, t128, barid);
        unsigned short* ord = half ? s->order1 : s->order0;
        for (int i = t128; i < NEDGE; i += 128)
            ord[i] = (unsigned short)(sb[i] & 0xffffu);
    }
    __syncthreads();

    // ---- 7. zero cnt matrices (alias sortbuf) + scatter labeled pixels ----
    {
        unsigned* c32 = (unsigned*)s->big;
        for (int i = tid; i < 2 * 65536 / 4; i += NTHREADS) c32[i] = 0;
    }
    __syncthreads();
    {
        unsigned short (*c0)[32] = (unsigned short(*)[32])(s->big[0]);
        unsigned short (*c1)[32] = (unsigned short(*)[32])(s->big[1]);
        for (int px = tid; px < NPX; px += NTHREADS) {
            int l = s->lab[px];
            if (l) {
                int c = s->cid[l - 1];
                if (c < 32) { c0[px][c] = 1; c1[px][c] = 1; }
            }
        }
    }
    __syncthreads();

    // ---- 8. pipelined Kruskal (producers: warps 0,1) + replay (consumers: 2,3) ----
    {
        int wid = tid >> 5;
        int L = s->Lval;
        if      (wid == 0) kruskal_warp(s, 0, s->order0);
        else if (wid == 1) kruskal_warp(s, 1, s->order1);
        else if (wid == 2) replay_consumer(s, 0, L, false);
        else if (wid == 3) replay_consumer(s, 1, L, true);
    }
    __syncthreads();

    // ---- 9. normalize, mask, gather to nodes, loss ----
    float vn = 0.0f, vp = 0.0f;
    for (int e = tid; e < NEDGE; e += NTHREADS) {
        vn += s->w0[e];
        vp += s->w1[e];
    }
    float sn = block_reduce(s, vn);
    float sp = block_reduce(s, vp);

    for (int e = tid; e < NEDGE; e += NTHREADS) {
        unsigned char f = s->eflags[e];
        float a = s->w0[e];
        if (sn > 0.0f) a /= sn;
        s->w0[e] = (f & 1) ? a : 0.0f;
        float bb = s->w1[e];
        if (sp > 0.0f) bb /= sp;
        s->w1[e] = (f & 2) ? bb : 0.0f;
    }
    __syncthreads();

    float lrn = lrn_p[0];
    float lrp = lrp_p[0];
    float acc = 0.0f;
    for (int px = tid; px < NPX; px += NTHREADS) {
        int y = px >> 5, x = px & 31;
        float wn = 0.0f, wp = 0.0f;
        if (x > 0)  { int e = y * 31 + x - 1; wn += s->w0[e]; wp += s->w1[e]; }
        if (x < 31) { int e = y * 31 + x;     wn += s->w0[e]; wp += s->w1[e]; }
        if (y > 0)  { int e = NH + px - 32;   wn += s->w0[e]; wp += s->w1[e]; }
        if (y < 31) { int e = NH + px;        wn += s->w0[e]; wp += s->w1[e]; }
        float p = s->pred[px];
        float d = 20.0f - p;
        acc += lrn * p * p * wn + lrp * d * d * wp;
    }
    float total = block_reduce(s, acc);
    if (tid == 0) atomicAdd(out, total);
}

extern "C" void kernel_launch(void* const* d_in, const int* in_sizes, int n_in,
                              void* d_out, int out_size) {
    const float* pred   = (const float*)d_in[0];
    const float* target = (const float*)d_in[1];
    const float* lrn    = (const float*)d_in[2];
    const float* lrp    = (const float*)d_in[3];
    float* out = (float*)d_out;

    const int HW = 256;
    int B = in_sizes[0] / (HW * HW);
    int nblocks = B * (HW / WIN) * (HW / WIN);

    cudaFuncSetAttribute(malis_kernel,
                         cudaFuncAttributeMaxDynamicSharedMemorySize,
                         (int)sizeof(Smem));

    zero_kernel<<<(out_size + NTHREADS - 1) / NTHREADS, NTHREADS>>>(out, out_size);
    malis_kernel<<<nblocks, NTHREADS, sizeof(Smem)>>>(pred, target, lrn, lrp, out, HW);
}